// round 7
// baseline (speedup 1.0000x reference)
#include <cuda_runtime.h>

// DigitCaps dynamic routing, GB300 sm_103a — R7.
// B=64, I=4096, Din=8, N=10, D=16, 3 routing iterations.
//
// R7 vs R6 (107.9us; k_pass additive fma(800)+L1(1500)+alu(350) cyc/SM-il):
//  - s_x XOR swizzle (float4 idx ^ (bb&7)): x LDS 2-way conflict gone (16->8 wf)
//  - Z split across dh partners: 5 LDS each + shfl-pair (was 10 LDS)
//  - W prefetch via cp.async.cg 16B: no STS wavefronts, no staging regs
//  - loop-carried pointers for g_blog / W src; unroll 2

#define B_ 64
#define I_ 4096
#define P_ 8
#define N_ 10
#define D_ 16
#define ND_ 160
#define THREADS 320
#define OUT_ (B_ * ND_)
#define L2E 1.4426950408889634f

// dynamic smem (floats)
#define SX_SZ (32 * 256)         // 32 rows x 64 float4 (swizzled)
#define SW_SZ (2 * 1280)
#define SE_SZ (2 * 352)
#define SMEM_BYTES ((SX_SZ + SW_SZ + SE_SZ) * 4)   // 45,824 B (< 48K default)

__device__ float g_part[(size_t)148 * OUT_];
__device__ float g_blog[(size_t)I_ * 640];      // log2-domain logits [i][n*64+bh*32+l]
__device__ float g_v[OUT_];
__device__ float g_pad;

typedef unsigned long long ull;

static __device__ __forceinline__ ull pack2(float a, float b) {
    ull r; asm("mov.b64 %0, {%1,%2};" : "=l"(r) : "f"(a), "f"(b)); return r;
}
static __device__ __forceinline__ float2 unpack2(ull v) {
    float2 r; asm("mov.b64 {%0,%1}, %2;" : "=f"(r.x), "=f"(r.y) : "l"(v)); return r;
}
static __device__ __forceinline__ ull ffma2(ull a, ull b, ull c) {
    ull d; asm("fma.rn.f32x2 %0, %1, %2, %3;" : "=l"(d) : "l"(a), "l"(b), "l"(c)); return d;
}
static __device__ __forceinline__ ull fadd2(ull a, ull b) {
    ull d; asm("add.rn.f32x2 %0, %1, %2;" : "=l"(d) : "l"(a), "l"(b)); return d;
}
static __device__ __forceinline__ float fast_ex2(float x) {
    float r; asm("ex2.approx.f32 %0, %1;" : "=f"(r) : "f"(x)); return r;
}
static __device__ __forceinline__ void cp16(unsigned dst, const void* src) {
    asm volatile("cp.async.cg.shared.global [%0], [%1], 16;" :: "r"(dst), "l"(src));
}
static __device__ __forceinline__ void cp_commit() {
    asm volatile("cp.async.commit_group;");
}
static __device__ __forceinline__ void cp_wait0() {
    asm volatile("cp.async.wait_group 0;" ::: "memory");
}

__global__ void k_pad() { g_pad = 0.0f; }

template <int PASS>
__global__ __launch_bounds__(THREADS, 2) void k_pass(const float* __restrict__ X,
                                                     const float* __restrict__ W) {
    extern __shared__ float smem[];
    float4* s_x4 = (float4*)smem;        // [lb][f^(lb&7)] 32 x 64 float4
    float*  s_w  = smem + SX_SZ;         // 2 x 1280
    float*  s_e  = s_w + SW_SZ;          // 2 x (32*11)

    const int tid = threadIdx.x;
    const int n   = tid >> 5;
    const int l   = tid & 31;
    const int bb  = l & 15;
    const int dh  = l >> 4;
    const int swz = bb & 7;
    const int cb  = blockIdx.x;
    const int bh  = blockIdx.y;
    int i0, ni;
    if (cb < 100) { i0 = cb * 28; ni = 28; }
    else          { i0 = 2800 + (cb - 100) * 27; ni = 27; }
    const int b1 = bh * 32 + bb;
    const int b2 = b1 + 16;

    // ---- stage x (swizzled float4 stores)
    {
        int nf = ni * 2;                            // float4 per row
        for (int idx = tid; idx < 32 * nf; idx += THREADS) {
            int lb = idx / nf;
            int f  = idx - lb * nf;
            float4 val = ((const float4*)(X + (size_t)(bh * 32 + lb) * (I_ * P_) + i0 * P_))[f];
            s_x4[lb * 64 + (f ^ (lb & 7))] = val;
        }
    }
    // ---- stage W(0) via cp.async
    unsigned swbase = (unsigned)__cvta_generic_to_shared(s_w);
    cp16(swbase + tid * 16, W + (size_t)i0 * 1280 + tid * 4);
    cp_commit();

    // ---- v (log2-scaled)
    ull v2a[4], v2b[4];
    if (PASS > 0) {
        const float4* va = (const float4*)(g_v + b1 * ND_ + n * D_ + dh * 8);
        const float4* vb = (const float4*)(g_v + b2 * ND_ + n * D_ + dh * 8);
        float4 a0 = va[0], a1 = va[1], c0 = vb[0], c1 = vb[1];
        v2a[0] = pack2(a0.x * L2E, a0.y * L2E); v2a[1] = pack2(a0.z * L2E, a0.w * L2E);
        v2a[2] = pack2(a1.x * L2E, a1.y * L2E); v2a[3] = pack2(a1.z * L2E, a1.w * L2E);
        v2b[0] = pack2(c0.x * L2E, c0.y * L2E); v2b[1] = pack2(c0.z * L2E, c0.w * L2E);
        v2b[2] = pack2(c1.x * L2E, c1.y * L2E); v2b[3] = pack2(c1.z * L2E, c1.w * L2E);
    }
    cp_wait0();
    __syncthreads();

    ull t2a[4], t2b[4], sa[4], sb[4];
#pragma unroll
    for (int j = 0; j < 4; j++) { sa[j] = 0ULL; sb[j] = 0ULL; }
    float e1p = 0.f, e2p = 0.f;

    const float* wsrc = W + (size_t)(i0 + 1) * 1280 + tid * 4;   // W(il+1) src
    float* gbp = g_blog + (size_t)i0 * 640 + n * 64 + bh * 32 + l;
    const float4* sxa = s_x4 + bb * 64;          // row b1
    const float4* sxb = s_x4 + (bb + 16) * 64;   // row b2 (same swz: (bb+16)&7==bb&7)

#pragma unroll 2
    for (int il = 0; il < ni; il++) {
        const int cur = il & 1;
        const bool wok = (il + 1 < ni);

        // ---- async W(il+1) prefetch into other buffer
        if (wok) {
            cp16(swbase + (1 - cur) * 5120 + tid * 16, wsrc);
            cp_commit();
            wsrc += 1280;
        }
        // ---- (pass2) prior logit
        float gb1 = 0.f, gb2 = 0.f;
        if (PASS == 2) {
            float go = *gbp;
            float gt = __shfl_xor_sync(0xffffffffu, go, 16);
            gb1 = dh ? gt : go;
            gb2 = dh ? go : gt;
        }

        // ---- consume stage il-1 (t2 holds t(il-1); e(il-1) in s_e[1-cur])
        if (il > 0) {
            if (PASS > 0) {
                const float* se = s_e + (1 - cur) * 352;
                const float* r1 = se + l * 11;          // own row, first 5
                const float* r2 = se + (l ^ 16) * 11;   // partner row, last 5
                float S1 = ((r1[0] + r1[1]) + (r1[2] + r1[3])) + r1[4];
                float S2 = ((r2[5] + r2[6]) + (r2[7] + r2[8])) + r2[9];
                float S1r = __shfl_xor_sync(0xffffffffu, S1, 16);
                float S2r = __shfl_xor_sync(0xffffffffu, S2, 16);
                float Zl  = S1 + S2r;    // Z of row l
                float Zlx = S1r + S2;    // Z of row l^16
                float Z1 = dh ? Zlx : Zl;
                float Z2 = dh ? Zl : Zlx;
                float c1 = __fdividef(e1p, Z1);
                float c2 = __fdividef(e2p, Z2);
                ull cp1 = pack2(c1, c1), cp2 = pack2(c2, c2);
#pragma unroll
                for (int j = 0; j < 4; j++) {
                    sa[j] = ffma2(cp1, t2a[j], sa[j]);
                    sb[j] = ffma2(cp2, t2b[j], sb[j]);
                }
            } else {
#pragma unroll
                for (int j = 0; j < 4; j++) {
                    sa[j] = fadd2(sa[j], t2a[j]);
                    sb[j] = fadd2(sb[j], t2b[j]);
                }
            }
        }

        // ---- x(il): swizzled float4 pairs
        float xa[8], xb[8];
        {
            int c0i = (il * 2) ^ swz;
            int c1i = c0i ^ 1;
            float4 a0 = sxa[c0i], a1 = sxa[c1i];
            float4 c0 = sxb[c0i], c1 = sxb[c1i];
            xa[0] = a0.x; xa[1] = a0.y; xa[2] = a0.z; xa[3] = a0.w;
            xa[4] = a1.x; xa[5] = a1.y; xa[6] = a1.z; xa[7] = a1.w;
            xb[0] = c0.x; xb[1] = c0.y; xb[2] = c0.z; xb[3] = c0.w;
            xb[4] = c1.x; xb[5] = c1.y; xb[6] = c1.z; xb[7] = c1.w;
        }

        // ---- t(il) = u[b, i, n, d-half] for both batches
#pragma unroll
        for (int j = 0; j < 4; j++) { t2a[j] = 0ULL; t2b[j] = 0ULL; }
        {
            const float* wb = s_w + cur * 1280 + n * 128 + dh * 8;
#pragma unroll
            for (int p = 0; p < P_; p++) {
                ull xpa = pack2(xa[p], xa[p]);
                ull xpb = pack2(xb[p], xb[p]);
                ulonglong2 w0 = *(const ulonglong2*)(wb + p * 16);
                ulonglong2 w1 = *(const ulonglong2*)(wb + p * 16 + 4);
                t2a[0] = ffma2(xpa, w0.x, t2a[0]); t2a[1] = ffma2(xpa, w0.y, t2a[1]);
                t2a[2] = ffma2(xpa, w1.x, t2a[2]); t2a[3] = ffma2(xpa, w1.y, t2a[3]);
                t2b[0] = ffma2(xpb, w0.x, t2b[0]); t2b[1] = ffma2(xpb, w0.y, t2b[1]);
                t2b[2] = ffma2(xpb, w1.x, t2b[2]); t2b[3] = ffma2(xpb, w1.y, t2b[3]);
            }
        }

        // ---- agreement + exp (log2 domain)
        if (PASS > 0) {
            ull aa = 0ULL, ab = 0ULL;
#pragma unroll
            for (int j = 0; j < 4; j++) {
                aa = ffma2(t2a[j], v2a[j], aa);
                ab = ffma2(t2b[j], v2b[j], ab);
            }
            float2 fa = unpack2(aa); float pa = fa.x + fa.y;
            float2 fb = unpack2(ab); float pb = fb.x + fb.y;
            float pao = __shfl_xor_sync(0xffffffffu, pa, 16);
            float pbo = __shfl_xor_sync(0xffffffffu, pb, 16);
            float bn1 = pa + pao + gb1;
            float bn2 = pb + pbo + gb2;
            if (PASS == 1) *gbp = dh ? bn2 : bn1;
            e1p = fast_ex2(bn1);
            e2p = fast_ex2(bn2);
            s_e[cur * 352 + l * 11 + n] = dh ? e2p : e1p;
        }
        if (PASS > 0) gbp += 640;

        if (wok) cp_wait0();
        __syncthreads();
    }

    // ---- epilogue: consume last stage
    {
        const int prev = (ni - 1) & 1;
        if (PASS > 0) {
            const float* se = s_e + prev * 352;
            const float* r1 = se + l * 11;
            const float* r2 = se + (l ^ 16) * 11;
            float S1 = ((r1[0] + r1[1]) + (r1[2] + r1[3])) + r1[4];
            float S2 = ((r2[5] + r2[6]) + (r2[7] + r2[8])) + r2[9];
            float S1r = __shfl_xor_sync(0xffffffffu, S1, 16);
            float S2r = __shfl_xor_sync(0xffffffffu, S2, 16);
            float Zl  = S1 + S2r;
            float Zlx = S1r + S2;
            float Z1 = dh ? Zlx : Zl;
            float Z2 = dh ? Zl : Zlx;
            float c1 = __fdividef(e1p, Z1);
            float c2 = __fdividef(e2p, Z2);
            ull cp1 = pack2(c1, c1), cp2 = pack2(c2, c2);
#pragma unroll
            for (int j = 0; j < 4; j++) {
                sa[j] = ffma2(cp1, t2a[j], sa[j]);
                sb[j] = ffma2(cp2, t2b[j], sb[j]);
            }
        } else {
#pragma unroll
            for (int j = 0; j < 4; j++) {
                sa[j] = fadd2(sa[j], t2a[j]);
                sb[j] = fadd2(sb[j], t2b[j]);
            }
        }
    }

    // ---- per-chunk partials (deterministic)
    {
        float* p1 = g_part + (size_t)cb * OUT_ + b1 * ND_ + n * D_ + dh * 8;
        float* p2 = g_part + (size_t)cb * OUT_ + b2 * ND_ + n * D_ + dh * 8;
        float2 a0 = unpack2(sa[0]), a1 = unpack2(sa[1]);
        float2 a2 = unpack2(sa[2]), a3 = unpack2(sa[3]);
        float2 c0 = unpack2(sb[0]), c1 = unpack2(sb[1]);
        float2 c2 = unpack2(sb[2]), c3 = unpack2(sb[3]);
        float k = (PASS == 0) ? 0.1f : 1.0f;
        *(float4*)(p1)     = make_float4(a0.x * k, a0.y * k, a1.x * k, a1.y * k);
        *(float4*)(p1 + 4) = make_float4(a2.x * k, a2.y * k, a3.x * k, a3.y * k);
        *(float4*)(p2)     = make_float4(c0.x * k, c0.y * k, c1.x * k, c1.y * k);
        *(float4*)(p2 + 4) = make_float4(c2.x * k, c2.y * k, c3.x * k, c3.y * k);
    }
}

// 148-way reduction + squash. Grid 320 x 512: 16 slices (4x10 + 12x9 = 148).
template <bool FINAL>
__global__ __launch_bounds__(512) void k_finish(float* __restrict__ dout) {
    __shared__ float red[16][33];
    int tid = threadIdx.x;
    int s = tid >> 5;
    int ol = tid & 31;
    int o = blockIdx.x * 32 + ol;

    int start = (s < 4) ? s * 10 : 40 + (s - 4) * 9;
    int cnt = (s < 4) ? 10 : 9;
    const float* p = g_part + (size_t)start * OUT_ + o;
    float a0 = 0.f, a1 = 0.f, a2 = 0.f, a3 = 0.f;
    int k = 0;
    for (; k + 4 <= cnt; k += 4) {
        a0 += p[(size_t)(k + 0) * OUT_];
        a1 += p[(size_t)(k + 1) * OUT_];
        a2 += p[(size_t)(k + 2) * OUT_];
        a3 += p[(size_t)(k + 3) * OUT_];
    }
    for (; k < cnt; k++) a0 += p[(size_t)k * OUT_];
    red[s][ol] = (a0 + a1) + (a2 + a3);
    __syncthreads();

    if (s == 0) {
        float t0 = (red[0][ol] + red[1][ol]) + (red[2][ol] + red[3][ol]);
        float t1 = (red[4][ol] + red[5][ol]) + (red[6][ol] + red[7][ol]);
        float t2 = (red[8][ol] + red[9][ol]) + (red[10][ol] + red[11][ol]);
        float t3 = (red[12][ol] + red[13][ol]) + (red[14][ol] + red[15][ol]);
        float sv = (t0 + t1) + (t2 + t3);
        float sq = sv * sv;
        float scale = sq / ((1.f + sq) * sqrtf(sq + 1e-7f));
        float v = scale * sv;
        if (FINAL) dout[o] = v;
        else       g_v[o] = v;
    }
}

extern "C" void kernel_launch(void* const* d_in, const int* in_sizes, int n_in,
                              void* d_out, int out_size) {
    const float* X = (const float*)d_in[0];
    const float* W = (const float*)d_in[1];
    if (n_in >= 2 && in_sizes[0] != B_ * I_ * P_) {
        const float* tmp = X; X = W; W = tmp;
    }

    dim3 gp(148, 2);
    k_pad<<<1, 1>>>();
    k_pass<0><<<gp, THREADS, SMEM_BYTES>>>(X, W);
    k_finish<false><<<320, 512>>>(nullptr);
    k_pass<1><<<gp, THREADS, SMEM_BYTES>>>(X, W);
    k_finish<false><<<320, 512>>>(nullptr);
    k_pass<2><<<gp, THREADS, SMEM_BYTES>>>(X, W);
    k_finish<true><<<320, 512>>>((float*)d_out);
}

// round 8
// speedup vs baseline: 1.0062x; 1.0062x over previous
#include <cuda_runtime.h>

// DigitCaps dynamic routing, GB300 sm_103a — R8.
// B=64, I=4096, Din=8, N=10, D=16, 3 routing iterations.
//
// R8 vs R7 (107.9 best; k_pass latency/convoy-bound, no pipe >53%):
//  - 4 independent 160-thread blocks/SM (5 warps: lane = 2n x 8bb x 2dh,
//    BTILE=2): barrier domains 4x more numerous, 2x narrower -> decorrelate
//  - pass0 specialized: no softmax, quad-buffered W, barrier every 2 il
//  - softmax exchange: dh partner = shfl_xor 8, Z-split partner = shfl_xor 16

#define B_ 64
#define I_ 4096
#define P_ 8
#define N_ 10
#define D_ 16
#define ND_ 160
#define THREADS 160
#define OUT_ (B_ * ND_)
#define L2E 1.4426950408889634f

// dynamic smem (floats): x 4096 + W 4x1280 + e 2x176
#define SX_F 4096                 // 16 rows x 64 float4
#define SW_F (4 * 1280)
#define SE_F (2 * 176)
#define SMEM_BYTES ((SX_F + SW_F + SE_F) * 4)   // 38,272 B

__device__ float g_part[(size_t)148 * OUT_];
__device__ float g_blog[(size_t)I_ * 640];      // log2-domain logits [i][n*64 + b]
__device__ float g_v[OUT_];
__device__ float g_pad;

typedef unsigned long long ull;

static __device__ __forceinline__ ull pack2(float a, float b) {
    ull r; asm("mov.b64 %0, {%1,%2};" : "=l"(r) : "f"(a), "f"(b)); return r;
}
static __device__ __forceinline__ float2 unpack2(ull v) {
    float2 r; asm("mov.b64 {%0,%1}, %2;" : "=f"(r.x), "=f"(r.y) : "l"(v)); return r;
}
static __device__ __forceinline__ ull ffma2(ull a, ull b, ull c) {
    ull d; asm("fma.rn.f32x2 %0, %1, %2, %3;" : "=l"(d) : "l"(a), "l"(b), "l"(c)); return d;
}
static __device__ __forceinline__ ull fadd2(ull a, ull b) {
    ull d; asm("add.rn.f32x2 %0, %1, %2;" : "=l"(d) : "l"(a), "l"(b)); return d;
}
static __device__ __forceinline__ float fast_ex2(float x) {
    float r; asm("ex2.approx.f32 %0, %1;" : "=f"(r) : "f"(x)); return r;
}
static __device__ __forceinline__ void cp16(unsigned dst, const void* src) {
    asm volatile("cp.async.cg.shared.global [%0], [%1], 16;" :: "r"(dst), "l"(src));
}
static __device__ __forceinline__ void cp_commit() {
    asm volatile("cp.async.commit_group;");
}
static __device__ __forceinline__ void cp_wait0() {
    asm volatile("cp.async.wait_group 0;" ::: "memory");
}

__global__ void k_pad() { g_pad = 0.0f; }

template <int PASS>
__global__ __launch_bounds__(THREADS, 4) void k_pass(const float* __restrict__ X,
                                                     const float* __restrict__ W) {
    extern __shared__ float smem[];
    float4* s_x4 = (float4*)smem;        // [lb<16][f4<64] swizzled
    float*  s_w  = smem + SX_F;          // [4][1280] (pass0 quad; pass1/2 use &1)
    float*  s_e  = s_w + SW_F;           // [2][16][11]

    const int tid = threadIdx.x;
    const int w   = tid >> 5;            // warp 0..4
    const int l   = tid & 31;
    const int n1  = l >> 4;
    const int dh  = (l >> 3) & 1;
    const int bb  = l & 7;
    const int n   = w * 2 + n1;          // capsule-out (warp covers 2 n's)
    const int cb  = blockIdx.x;          // i-chunk
    const int bg  = blockIdx.y;          // batch group (16 batches)
    int i0, ni;
    if (cb < 100) { i0 = cb * 28; ni = 28; }
    else          { i0 = 2800 + (cb - 100) * 27; ni = 27; }
    const int row_e = dh * 8 + bb;       // local batch row this lane owns (= l&15)
    const int b1 = bg * 16 + bb;         // global batches for this thread
    const int b2 = b1 + 8;

    // ---- stage x: 16 local batches x ni*8 floats, swizzled float4
    {
        int nf = ni * 2;
        for (int idx = tid; idx < 16 * nf; idx += THREADS) {
            int lb = idx / nf;
            int f  = idx - lb * nf;
            float4 val = ((const float4*)(X + (size_t)(bg * 16 + lb) * (I_ * P_) + i0 * P_))[f];
            s_x4[lb * 64 + (f ^ (lb & 7))] = val;
        }
    }
    // ---- stage W(0), W(1) via cp.async (each thread: 8 floats per il)
    unsigned swb = (unsigned)__cvta_generic_to_shared(s_w);
    {
        const float* ws = W + (size_t)i0 * 1280 + tid * 8;
        cp16(swb + (tid * 8) * 4, ws);
        cp16(swb + (tid * 8 + 4) * 4, ws + 4);
        if (ni > 1) {
            cp16(swb + (1280 + tid * 8) * 4, ws + 1280);
            cp16(swb + (1280 + tid * 8 + 4) * 4, ws + 1284);
        }
        cp_commit();
    }
    // ---- v (log2-scaled) for both batches, this thread's (n, d-half)
    ull v2a[4], v2b[4];
    if (PASS > 0) {
        const float4* va = (const float4*)(g_v + b1 * ND_ + n * D_ + dh * 8);
        const float4* vb = (const float4*)(g_v + b2 * ND_ + n * D_ + dh * 8);
        float4 a0 = va[0], a1 = va[1], c0 = vb[0], c1 = vb[1];
        v2a[0] = pack2(a0.x * L2E, a0.y * L2E); v2a[1] = pack2(a0.z * L2E, a0.w * L2E);
        v2a[2] = pack2(a1.x * L2E, a1.y * L2E); v2a[3] = pack2(a1.z * L2E, a1.w * L2E);
        v2b[0] = pack2(c0.x * L2E, c0.y * L2E); v2b[1] = pack2(c0.z * L2E, c0.w * L2E);
        v2b[2] = pack2(c1.x * L2E, c1.y * L2E); v2b[3] = pack2(c1.z * L2E, c1.w * L2E);
    }
    cp_wait0();
    __syncthreads();

    ull t2a[4], t2b[4], sa[4], sb[4];
#pragma unroll
    for (int j = 0; j < 4; j++) { sa[j] = 0ULL; sb[j] = 0ULL; }
    float e1p = 0.f, e2p = 0.f;

    const float* wsrc = W + (size_t)(i0 + 2) * 1280 + tid * 8;
    float* gbp = g_blog + (size_t)i0 * 640 + n * 64 + bg * 16 + row_e;
    const float4* sxa = s_x4 + bb * 64;
    const float4* sxb = s_x4 + (bb + 8) * 64;

    for (int il = 0; il < ni; il++) {
        const int cur = il & 1;

        // ---- W staging
        if (PASS == 0) {
            // quad-buffered, stage (il+2, il+3) at even il
            if ((il & 1) == 0) {
                if (il + 2 < ni) {
                    unsigned d2 = swb + (((il + 2) & 3) * 1280 + tid * 8) * 4;
                    cp16(d2, wsrc); cp16(d2 + 16, wsrc + 4);
                    wsrc += 1280;
                    if (il + 3 < ni) {
                        unsigned d3 = swb + (((il + 3) & 3) * 1280 + tid * 8) * 4;
                        cp16(d3, wsrc); cp16(d3 + 16, wsrc + 4);
                        wsrc += 1280;
                    }
                    cp_commit();
                }
            }
        } else {
            // double-buffered, stage (il+2) into slot (il+2)&1 = cur (consumed il done)
            // NOTE: slot `cur` is being read THIS il -> stage into (il+2)&1 only after
            // barrier; instead stage 1-ahead like R6: W(il+1) already staged last il.
            if (il + 2 < ni) {
                unsigned d2 = swb + (((il + 2) & 1) * 1280 + tid * 8) * 4;
                // (il+2)&1 == il&1 == cur: slot cur is read this il BEFORE barrier,
                // but cp.async writes land asynchronously... must not overwrite early.
                // Safe ordering: issue AFTER our reads? Not guaranteed across warps.
                // -> stage at END of loop body instead (below). placeholder
                (void)d2;
            }
        }
        // ---- (pass2) prior logit for both batches
        float gb1 = 0.f, gb2 = 0.f;
        if (PASS == 2) {
            float go = *gbp;
            float gt = __shfl_xor_sync(0xffffffffu, go, 8);
            gb1 = dh ? gt : go;
            gb2 = dh ? go : gt;
        }

        // ---- consume stage il-1
        if (PASS > 0) {
            if (il > 0) {
                const float* se = s_e + (1 - cur) * 176 + row_e * 11 + n1 * 5;
                float S = ((se[0] + se[1]) + (se[2] + se[3])) + se[4];
                float Sp = __shfl_xor_sync(0xffffffffu, S, 16);
                float Zrow = S + Sp;                                  // Z of batch row_e
                float Zo = __shfl_xor_sync(0xffffffffu, Zrow, 8);     // Z of other batch
                float Z1 = dh ? Zo : Zrow;
                float Z2 = dh ? Zrow : Zo;
                float c1 = __fdividef(e1p, Z1);
                float c2 = __fdividef(e2p, Z2);
                ull cp1 = pack2(c1, c1), cp2 = pack2(c2, c2);
#pragma unroll
                for (int j = 0; j < 4; j++) {
                    sa[j] = ffma2(cp1, t2a[j], sa[j]);
                    sb[j] = ffma2(cp2, t2b[j], sb[j]);
                }
            }
        }

        // ---- x(il): swizzled float4 pairs, both batches
        float xa[8], xb[8];
        {
            int c0i = (il * 2) ^ bb;
            int c1i = c0i ^ 1;
            float4 a0 = sxa[c0i], a1 = sxa[c1i];
            float4 c0 = sxb[c0i], c1 = sxb[c1i];
            xa[0] = a0.x; xa[1] = a0.y; xa[2] = a0.z; xa[3] = a0.w;
            xa[4] = a1.x; xa[5] = a1.y; xa[6] = a1.z; xa[7] = a1.w;
            xb[0] = c0.x; xb[1] = c0.y; xb[2] = c0.z; xb[3] = c0.w;
            xb[4] = c1.x; xb[5] = c1.y; xb[6] = c1.z; xb[7] = c1.w;
        }

        // ---- t(il) = u[b, i, n, d-half], both batches
#pragma unroll
        for (int j = 0; j < 4; j++) { t2a[j] = 0ULL; t2b[j] = 0ULL; }
        {
            const int wslot = (PASS == 0) ? (il & 3) : cur;
            const float* wb = s_w + wslot * 1280 + n * 128 + dh * 8;
#pragma unroll
            for (int p = 0; p < P_; p++) {
                ull xpa = pack2(xa[p], xa[p]);
                ull xpb = pack2(xb[p], xb[p]);
                ulonglong2 w0 = *(const ulonglong2*)(wb + p * 16);
                ulonglong2 w1 = *(const ulonglong2*)(wb + p * 16 + 4);
                t2a[0] = ffma2(xpa, w0.x, t2a[0]); t2a[1] = ffma2(xpa, w0.y, t2a[1]);
                t2a[2] = ffma2(xpa, w1.x, t2a[2]); t2a[3] = ffma2(xpa, w1.y, t2a[3]);
                t2b[0] = ffma2(xpb, w0.x, t2b[0]); t2b[1] = ffma2(xpb, w0.y, t2b[1]);
                t2b[2] = ffma2(xpb, w1.x, t2b[2]); t2b[3] = ffma2(xpb, w1.y, t2b[3]);
            }
        }

        if (PASS == 0) {
            // immediate accumulate (uniform c), scaled at store
#pragma unroll
            for (int j = 0; j < 4; j++) {
                sa[j] = fadd2(sa[j], t2a[j]);
                sb[j] = fadd2(sb[j], t2b[j]);
            }
            if ((il & 1) == 1 || il == ni - 1) { cp_wait0(); __syncthreads(); }
        } else {
            // ---- agreement (d-half partial + dh-partner shfl), logits, exp
            ull aa = 0ULL, ab = 0ULL;
#pragma unroll
            for (int j = 0; j < 4; j++) {
                aa = ffma2(t2a[j], v2a[j], aa);
                ab = ffma2(t2b[j], v2b[j], ab);
            }
            float2 fa = unpack2(aa); float pa = fa.x + fa.y;
            float2 fb = unpack2(ab); float pb = fb.x + fb.y;
            float pao = __shfl_xor_sync(0xffffffffu, pa, 8);   // other d-half, batch b1
            float pbo = __shfl_xor_sync(0xffffffffu, pb, 8);   // other d-half, batch b2
            float bn1 = pa + pao + gb1;
            float bn2 = pb + pbo + gb2;
            *gbp = dh ? bn2 : bn1;                // own-row logit (PASS1 init / PASS2 update)
            e1p = fast_ex2(bn1);
            e2p = fast_ex2(bn2);
            s_e[cur * 176 + row_e * 11 + n] = dh ? e2p : e1p;
            gbp += 640;

            // ---- stage W(il+1) now (slot (il+1)&1 = 1-cur; protected by prior barrier)
            if (il + 1 < ni) {
                const float* ws1 = W + (size_t)(i0 + il + 1) * 1280 + tid * 8;
                unsigned d1 = swb + (((il + 1) & 1) * 1280 + tid * 8) * 4;
                cp16(d1, ws1); cp16(d1 + 16, ws1 + 4);
                cp_commit();
            }
            cp_wait0();
            __syncthreads();
        }
    }

    // ---- epilogue: consume last stage (PASS>0)
    if (PASS > 0) {
        const int prev = (ni - 1) & 1;
        const float* se = s_e + prev * 176 + row_e * 11 + n1 * 5;
        float S = ((se[0] + se[1]) + (se[2] + se[3])) + se[4];
        float Sp = __shfl_xor_sync(0xffffffffu, S, 16);
        float Zrow = S + Sp;
        float Zo = __shfl_xor_sync(0xffffffffu, Zrow, 8);
        float Z1 = dh ? Zo : Zrow;
        float Z2 = dh ? Zrow : Zo;
        float c1 = __fdividef(e1p, Z1);
        float c2 = __fdividef(e2p, Z2);
        ull cp1 = pack2(c1, c1), cp2 = pack2(c2, c2);
#pragma unroll
        for (int j = 0; j < 4; j++) {
            sa[j] = ffma2(cp1, t2a[j], sa[j]);
            sb[j] = ffma2(cp2, t2b[j], sb[j]);
        }
    }

    // ---- per-chunk partials (deterministic; same layout as output)
    {
        float* p1 = g_part + (size_t)cb * OUT_ + b1 * ND_ + n * D_ + dh * 8;
        float* p2 = g_part + (size_t)cb * OUT_ + b2 * ND_ + n * D_ + dh * 8;
        float2 a0 = unpack2(sa[0]), a1 = unpack2(sa[1]);
        float2 a2 = unpack2(sa[2]), a3 = unpack2(sa[3]);
        float2 c0 = unpack2(sb[0]), c1 = unpack2(sb[1]);
        float2 c2 = unpack2(sb[2]), c3 = unpack2(sb[3]);
        float k = (PASS == 0) ? 0.1f : 1.0f;
        *(float4*)(p1)     = make_float4(a0.x * k, a0.y * k, a1.x * k, a1.y * k);
        *(float4*)(p1 + 4) = make_float4(a2.x * k, a2.y * k, a3.x * k, a3.y * k);
        *(float4*)(p2)     = make_float4(c0.x * k, c0.y * k, c1.x * k, c1.y * k);
        *(float4*)(p2 + 4) = make_float4(c2.x * k, c2.y * k, c3.x * k, c3.y * k);
    }
}

// 148-way reduction + squash. Grid 320 x 512: 16 slices (4x10 + 12x9 = 148).
template <bool FINAL>
__global__ __launch_bounds__(512) void k_finish(float* __restrict__ dout) {
    __shared__ float red[16][33];
    int tid = threadIdx.x;
    int s = tid >> 5;
    int ol = tid & 31;
    int o = blockIdx.x * 32 + ol;

    int start = (s < 4) ? s * 10 : 40 + (s - 4) * 9;
    int cnt = (s < 4) ? 10 : 9;
    const float* p = g_part + (size_t)start * OUT_ + o;
    float a0 = 0.f, a1 = 0.f, a2 = 0.f, a3 = 0.f;
    int k = 0;
    for (; k + 4 <= cnt; k += 4) {
        a0 += p[(size_t)(k + 0) * OUT_];
        a1 += p[(size_t)(k + 1) * OUT_];
        a2 += p[(size_t)(k + 2) * OUT_];
        a3 += p[(size_t)(k + 3) * OUT_];
    }
    for (; k < cnt; k++) a0 += p[(size_t)k * OUT_];
    red[s][ol] = (a0 + a1) + (a2 + a3);
    __syncthreads();

    if (s == 0) {
        float t0 = (red[0][ol] + red[1][ol]) + (red[2][ol] + red[3][ol]);
        float t1 = (red[4][ol] + red[5][ol]) + (red[6][ol] + red[7][ol]);
        float t2 = (red[8][ol] + red[9][ol]) + (red[10][ol] + red[11][ol]);
        float t3 = (red[12][ol] + red[13][ol]) + (red[14][ol] + red[15][ol]);
        float sv = (t0 + t1) + (t2 + t3);
        float sq = sv * sv;
        float scale = sq / ((1.f + sq) * sqrtf(sq + 1e-7f));
        float v = scale * sv;
        if (FINAL) dout[o] = v;
        else       g_v[o] = v;
    }
}

extern "C" void kernel_launch(void* const* d_in, const int* in_sizes, int n_in,
                              void* d_out, int out_size) {
    const float* X = (const float*)d_in[0];
    const float* W = (const float*)d_in[1];
    if (n_in >= 2 && in_sizes[0] != B_ * I_ * P_) {
        const float* tmp = X; X = W; W = tmp;
    }

    cudaFuncSetAttribute(k_pass<0>, cudaFuncAttributeMaxDynamicSharedMemorySize, SMEM_BYTES);
    cudaFuncSetAttribute(k_pass<1>, cudaFuncAttributeMaxDynamicSharedMemorySize, SMEM_BYTES);
    cudaFuncSetAttribute(k_pass<2>, cudaFuncAttributeMaxDynamicSharedMemorySize, SMEM_BYTES);

    dim3 gp(148, 4);
    k_pad<<<1, 1>>>();
    k_pass<0><<<gp, THREADS, SMEM_BYTES>>>(X, W);
    k_finish<false><<<320, 512>>>(nullptr);
    k_pass<1><<<gp, THREADS, SMEM_BYTES>>>(X, W);
    k_finish<false><<<320, 512>>>(nullptr);
    k_pass<2><<<gp, THREADS, SMEM_BYTES>>>(X, W);
    k_finish<true><<<320, 512>>>((float*)d_out);
}